// round 1
// baseline (speedup 1.0000x reference)
#include <cuda_runtime.h>

// Problem constants
#define C_IN   256
#define HW_IMG 16384      // 128*128
#define W_IMG  128
#define CK     2304       // C*3*3 (GEMM K)
#define NROI   8192       // GEMM N
#define FDIM   256        // GEMM M

// GEMM tiling
#define BM 64
#define BN 64
#define BK 32
#define NTHREADS 256

// ---------------------------------------------------------------------------
// Kernel 1: fill output with bias (out is poisoned 0xAA before timing).
// out[f, p] = bias[f] for all f, p. Vectorized float4.
// ---------------------------------------------------------------------------
__global__ __launch_bounds__(256) void bias_fill_kernel(
    const float* __restrict__ bias, float4* __restrict__ out)
{
    int i = blockIdx.x * blockDim.x + threadIdx.x;   // 0 .. F*HW/4-1
    float bv = __ldg(&bias[i >> 12]);                // 4096 float4 per f-row
    out[i] = make_float4(bv, bv, bv, bv);
}

// ---------------------------------------------------------------------------
// Kernel 2: implicit-im2col GEMM over roi columns.
// C[m0+.., j] = sum_k W[m][k] * X_patch[k][roi[j]]  ;  out[f*HW + p] = C + b[f]
// ---------------------------------------------------------------------------
__global__ __launch_bounds__(NTHREADS) void sparse_conv_gemm(
    const float* __restrict__ x,     // [256][128][128]
    const float* __restrict__ w,     // [256][2304]
    const float* __restrict__ bias,  // [256]
    const int*   __restrict__ roi,   // [8192] sorted
    float*       __restrict__ out)   // [256][16384]
{
    __shared__ float As[BK][BM + 4];  // [k][m], pitch 68 keeps float4 alignment
    __shared__ float Bs[BK][BN + 4];  // [k][n]
    __shared__ int   sh_h[BN], sh_w[BN], sh_p[BN];

    const int tid = threadIdx.x;
    const int n0  = blockIdx.x * BN;
    const int m0  = blockIdx.y * BM;

    if (tid < BN) {
        int p = __ldg(&roi[n0 + tid]);
        sh_p[tid] = p;
        sh_h[tid] = p >> 7;      // WO = 128
        sh_w[tid] = p & 127;
    }
    __syncthreads();

    const int tx = tid & 15;   // n-dim (4 cols each)
    const int ty = tid >> 4;   // m-dim (4 rows each)

    // Accumulators: 4 m-rows x 2 f32x2 pairs (= 4 n-cols). 0ull == (+0.f,+0.f)
    unsigned long long acc[4][2];
#pragma unroll
    for (int m = 0; m < 4; m++) { acc[m][0] = 0ull; acc[m][1] = 0ull; }

    for (int k0 = 0; k0 < CK; k0 += BK) {
        // ---- load A tile: W[m0+m][k0+k] -> As[k][m] (coalesced gmem reads)
#pragma unroll
        for (int r = 0; r < (BM * BK) / NTHREADS; r++) {
            int idx = tid + r * NTHREADS;
            int m = idx >> 5;          // /BK
            int k = idx & (BK - 1);
            As[k][m] = __ldg(&w[(m0 + m) * CK + k0 + k]);
        }
        // ---- load B tile (im2col gather): Bs[k][n]
#pragma unroll
        for (int r = 0; r < (BK * BN) / NTHREADS; r++) {
            int idx = tid + r * NTHREADS;
            int k = idx >> 6;          // /BN
            int n = idx & (BN - 1);
            int kk = k0 + k;
            int c  = kk / 9;
            int s  = kk - c * 9;
            int di = s / 3 - 1;
            int dj = s - (s / 3) * 3 - 1;
            int h  = sh_h[n] + di;
            int ww = sh_w[n] + dj;
            float v = 0.0f;
            if ((unsigned)h < 128u && (unsigned)ww < 128u)
                v = __ldg(&x[c * HW_IMG + h * W_IMG + ww]);
            Bs[k][n] = v;
        }
        __syncthreads();

        // ---- compute: 4x4 per thread via packed fma.rn.f32x2
#pragma unroll
        for (int k = 0; k < BK; k++) {
            float4 bv = *(const float4*)&Bs[k][tx * 4];
            float4 av = *(const float4*)&As[k][ty * 4];
            unsigned long long b01, b23;
            asm("mov.b64 %0, {%1, %2};" : "=l"(b01) : "f"(bv.x), "f"(bv.y));
            asm("mov.b64 %0, {%1, %2};" : "=l"(b23) : "f"(bv.z), "f"(bv.w));
            float am[4] = {av.x, av.y, av.z, av.w};
#pragma unroll
            for (int m = 0; m < 4; m++) {
                unsigned long long aa;
                asm("mov.b64 %0, {%1, %1};" : "=l"(aa) : "f"(am[m]));
                asm("fma.rn.f32x2 %0, %1, %2, %0;"
                    : "+l"(acc[m][0]) : "l"(aa), "l"(b01));
                asm("fma.rn.f32x2 %0, %1, %2, %0;"
                    : "+l"(acc[m][1]) : "l"(aa), "l"(b23));
            }
        }
        __syncthreads();
    }

    // ---- epilogue: scatter acc + bias to out[f*HW + p]
#pragma unroll
    for (int m = 0; m < 4; m++) {
        int f = m0 + ty * 4 + m;
        float bb = __ldg(&bias[f]);
        float v0, v1, v2, v3;
        asm("mov.b64 {%0, %1}, %2;" : "=f"(v0), "=f"(v1) : "l"(acc[m][0]));
        asm("mov.b64 {%0, %1}, %2;" : "=f"(v2), "=f"(v3) : "l"(acc[m][1]));
        float vals[4] = {v0, v1, v2, v3};
#pragma unroll
        for (int n = 0; n < 4; n++) {
            out[f * HW_IMG + sh_p[tx * 4 + n]] = vals[n] + bb;
        }
    }
}

// ---------------------------------------------------------------------------
extern "C" void kernel_launch(void* const* d_in, const int* in_sizes, int n_in,
                              void* d_out, int out_size)
{
    const float* x    = (const float*)d_in[0];   // input_x  (1,256,128,128)
    const float* w    = (const float*)d_in[1];   // input_w  (256,256,3,3)
    const float* b    = (const float*)d_in[2];   // input_b  (256,)
    const int*   roi  = (const int*)d_in[3];     // roi_idx  (8192,)
    float*       out  = (float*)d_out;           // (1,256,128,128)

    // 1) bias fill: 256*16384 floats = 1,048,576 float4
    bias_fill_kernel<<<4096, 256>>>(b, (float4*)out);

    // 2) sparse im2col GEMM + scatter (same stream -> ordered after fill)
    dim3 grid(NROI / BN, FDIM / BM);   // (128, 4)
    sparse_conv_gemm<<<grid, NTHREADS>>>(x, w, b, roi, out);
}

// round 3
// speedup vs baseline: 2.8762x; 2.8762x over previous
#include <cuda_runtime.h>
#include <cuda_bf16.h>

// ---------------- problem constants ----------------
#define CK     2304
#define HW     16384
#define FDIM   256
#define NROI   8192

// ---------------- GEMM config ----------------
#define BM     128
#define BN     128
#define BK     32
#define NIT    (CK / BK)        // 72
#define NTHR   256

#define APITCH 80               // bytes per smem row (40 bf16): 5*16 -> ldmatrix conflict-free
#define TILEB  (128 * APITCH)   // 10240 B per 128x32 bf16 tile
#define AH_OFF 0
#define AL_OFF (1 * TILEB)
#define BH_OFF (2 * TILEB)
#define BL_OFF (3 * TILEB)
#define STAGE  (4 * TILEB)      // 40960
#define SMEM_BYTES (2 * STAGE)  // 81920

// device scratch (allocation-free)
__device__ __nv_bfloat16 g_whi[FDIM * CK];
__device__ __nv_bfloat16 g_wlo[FDIM * CK];
__device__ unsigned      g_xpk[256 * HW];   // packed {lo16,hi16} of x

// ---------------- PTX helpers ----------------
__device__ __forceinline__ unsigned smem_u32(const void* p) {
    unsigned a;
    asm("{ .reg .u64 t; cvta.to.shared.u64 t, %1; cvt.u32.u64 %0, t; }" : "=r"(a) : "l"(p));
    return a;
}
#define LDSM4(r, a)                                                             \
    asm volatile("ldmatrix.sync.aligned.m8n8.x4.shared.b16 {%0,%1,%2,%3}, [%4];"\
        : "=r"((r)[0]), "=r"((r)[1]), "=r"((r)[2]), "=r"((r)[3]) : "r"(a))
#define MMA16816(c, a, b0, b1)                                                  \
    asm volatile("mma.sync.aligned.m16n8k16.row.col.f32.bf16.bf16.f32 "         \
        "{%0,%1,%2,%3}, {%4,%5,%6,%7}, {%8,%9}, {%0,%1,%2,%3};"                 \
        : "+f"((c)[0]), "+f"((c)[1]), "+f"((c)[2]), "+f"((c)[3])                \
        : "r"((a)[0]), "r"((a)[1]), "r"((a)[2]), "r"((a)[3]), "r"(b0), "r"(b1))
#define STS64(addr, v0, v1)                                                     \
    asm volatile("st.shared.v2.b32 [%0], {%1,%2};" :: "r"(addr), "r"(v0), "r"(v1) : "memory")
#define CPASYNC16(dst, src)                                                     \
    asm volatile("cp.async.cg.shared.global [%0], [%1], 16;" :: "r"(dst), "l"(src))
#define CPCOMMIT() asm volatile("cp.async.commit_group;" ::: "memory")
#define CPWAIT0()  asm volatile("cp.async.wait_group 0;"  ::: "memory")

// ---------------------------------------------------------------------------
// prep kernels
// ---------------------------------------------------------------------------
__global__ __launch_bounds__(512) void wsplit_kernel(const float* __restrict__ w) {
    int i = blockIdx.x * 512 + threadIdx.x;      // exact: 1152*512 = 589824
    float v = w[i];
    __nv_bfloat16 hi = __float2bfloat16(v);
    g_whi[i] = hi;
    g_wlo[i] = __float2bfloat16(v - __bfloat162float(hi));
}

__global__ __launch_bounds__(512) void xpack_kernel(const float* __restrict__ x) {
    int i = blockIdx.x * 512 + threadIdx.x;      // exact: 8192*512 = 4194304
    float v = x[i];
    __nv_bfloat16 hi = __float2bfloat16(v);
    __nv_bfloat16 lo = __float2bfloat16(v - __bfloat162float(hi));
    unsigned h = *(unsigned short*)&hi, l = *(unsigned short*)&lo;
    g_xpk[i] = h | (l << 16);
}

__global__ __launch_bounds__(256) void bias_fill_kernel(
    const float* __restrict__ bias, float4* __restrict__ out) {
    int i = blockIdx.x * blockDim.x + threadIdx.x;
    float bv = __ldg(&bias[i >> 12]);
    out[i] = make_float4(bv, bv, bv, bv);
}

// ---------------------------------------------------------------------------
// main: bf16x3 sparse-im2col GEMM via mma.sync m16n8k16
// ---------------------------------------------------------------------------
__global__ __launch_bounds__(NTHR, 1) void conv_mma(
    const float* __restrict__ bias, const int* __restrict__ roi,
    float* __restrict__ out)
{
    extern __shared__ char sm[];
    __shared__ int sh_p[128];
    const unsigned smbase = smem_u32(sm);

    const int tid = threadIdx.x, lane = tid & 31, wid = tid >> 5;
    const int n0 = blockIdx.x * BN, m0g = blockIdx.y * BM;

    if (tid < 128) sh_p[tid] = __ldg(&roi[n0 + tid]);
    __syncthreads();

    // gather-thread constants: each thread owns (n = tid&127, kq0 = tid>>7)
    const int gn = tid & 127;
    const int gkq0 = tid >> 7;
    const int gp = sh_p[gn];
    const int gh = gp >> 7, gw = gp & 127;

    // warp tile: 2(m) x 4(n) warps -> 64m x 32n per warp
    const int wm = (wid >> 2) * 64, wn = (wid & 3) * 32;
    const int l8 = lane & 7;
    const unsigned a_lane_off =
        (unsigned)((wm + ((lane >> 3) & 1) * 8 + l8) * APITCH + ((lane >> 4) * 8) * 2);
    const unsigned b_lane_off =
        (unsigned)((wn + (lane >> 4) * 8 + l8) * APITCH + (((lane >> 3) & 1) * 8) * 2);

    float acc[4][4][4];
#pragma unroll
    for (int a = 0; a < 4; a++)
#pragma unroll
        for (int b = 0; b < 4; b++)
#pragma unroll
            for (int c = 0; c < 4; c++) acc[a][b][c] = 0.0f;

    unsigned pk[4][4];

    // ---- stage loaders ----
    auto issue_A = [&](int it, int st) {
        const int k0 = it * BK;
        const unsigned dst0 = smbase + st * STAGE;
#pragma unroll
        for (int r = 0; r < 4; r++) {
            int c2 = r * NTHR + tid;           // 0..1023
            int half = c2 >> 9, m = (c2 >> 2) & 127, q = c2 & 3;
            const __nv_bfloat16* src =
                (half ? g_wlo : g_whi) + (m0g + m) * CK + k0 + q * 8;
            CPASYNC16(dst0 + half * TILEB + m * APITCH + q * 16, src);
        }
    };
    auto issue_B = [&](int it) {
        const int k0 = it * BK;
#pragma unroll
        for (int r = 0; r < 4; r++) {
            const int kq = gkq0 + r * 2;       // 0..7
#pragma unroll
            for (int j = 0; j < 4; j++) {
                int kk = k0 + kq * 4 + j;
                unsigned c = ((unsigned)kk * 7282u) >> 16;     // kk/9
                int s9 = kk - (int)c * 9;
                int di = (s9 * 11) >> 5;                       // s9/3
                int dj = s9 - di * 3;
                int hh = gh + di - 1, ww = gw + dj - 1;
                unsigned v = 0u;
                if ((unsigned)hh < 128u && (unsigned)ww < 128u)
                    v = __ldg(&g_xpk[(int)c * HW + hh * 128 + ww]);
                pk[r][j] = v;
            }
        }
    };
    auto store_B = [&](int st) {
        const unsigned dst0 = smbase + st * STAGE;
#pragma unroll
        for (int r = 0; r < 4; r++) {
            const int kq = gkq0 + r * 2;
            unsigned hp0 = __byte_perm(pk[r][0], pk[r][1], 0x5410);
            unsigned hp1 = __byte_perm(pk[r][2], pk[r][3], 0x5410);
            unsigned lp0 = __byte_perm(pk[r][0], pk[r][1], 0x7632);
            unsigned lp1 = __byte_perm(pk[r][2], pk[r][3], 0x7632);
            unsigned off = (unsigned)(gn * APITCH + kq * 8);
            STS64(dst0 + BH_OFF + off, hp0, hp1);
            STS64(dst0 + BL_OFF + off, lp0, lp1);
        }
    };
    auto compute = [&](int st) {
        const unsigned base = smbase + st * STAGE;
#pragma unroll
        for (int k16 = 0; k16 < 2; k16++) {
            unsigned ah[4][4], al[4][4];
#pragma unroll
            for (int mt = 0; mt < 4; mt++) {
                unsigned addr = base + AH_OFF + a_lane_off + mt * 16 * APITCH + k16 * 32;
                LDSM4(ah[mt], addr);
                LDSM4(al[mt], addr + TILEB);
            }
            unsigned bh[2][4], bl[2][4];
#pragma unroll
            for (int np = 0; np < 2; np++) {
                unsigned addr = base + BH_OFF + b_lane_off + np * 16 * APITCH + k16 * 32;
                LDSM4(bh[np], addr);
                LDSM4(bl[np], addr + TILEB);
            }
#pragma unroll
            for (int mt = 0; mt < 4; mt++)
#pragma unroll
                for (int nt = 0; nt < 4; nt++) {
                    int np = nt >> 1, s = (nt & 1) * 2;
                    MMA16816(acc[mt][nt], ah[mt], bh[np][s], bh[np][s + 1]);
                    MMA16816(acc[mt][nt], al[mt], bh[np][s], bh[np][s + 1]);
                    MMA16816(acc[mt][nt], ah[mt], bl[np][s], bl[np][s + 1]);
                }
        }
    };

    // ---- prologue ----
    issue_A(0, 0);
    CPCOMMIT();
    issue_B(0);
    store_B(0);
    CPWAIT0();
    __syncthreads();

    // ---- mainloop (double-buffered) ----
    for (int it = 0; it < NIT; it++) {
        const int cur = it & 1, nxt = cur ^ 1;
        const bool more = (it + 1) < NIT;
        if (more) {
            issue_A(it + 1, nxt);
            CPCOMMIT();
            issue_B(it + 1);
        }
        compute(cur);
        if (more) {
            store_B(nxt);
            CPWAIT0();
        }
        __syncthreads();
    }

    // ---- epilogue: scatter acc + bias ----
#pragma unroll
    for (int mt = 0; mt < 4; mt++) {
        const int f0 = m0g + wm + mt * 16 + (lane >> 2);
        const float b0 = __ldg(&bias[f0]);
        const float b1 = __ldg(&bias[f0 + 8]);
        float* o0 = out + f0 * HW;
        float* o1 = out + (f0 + 8) * HW;
#pragma unroll
        for (int nt = 0; nt < 4; nt++) {
            const int nl = wn + nt * 8 + 2 * (lane & 3);
            const int p0 = sh_p[nl], p1 = sh_p[nl + 1];
            o0[p0] = acc[mt][nt][0] + b0;
            o0[p1] = acc[mt][nt][1] + b0;
            o1[p0] = acc[mt][nt][2] + b1;
            o1[p1] = acc[mt][nt][3] + b1;
        }
    }
}

// ---------------------------------------------------------------------------
extern "C" void kernel_launch(void* const* d_in, const int* in_sizes, int n_in,
                              void* d_out, int out_size)
{
    const float* x   = (const float*)d_in[0];
    const float* w   = (const float*)d_in[1];
    const float* b   = (const float*)d_in[2];
    const int*   roi = (const int*)d_in[3];
    float*       out = (float*)d_out;

    cudaFuncSetAttribute(conv_mma,
                         cudaFuncAttributeMaxDynamicSharedMemorySize, SMEM_BYTES);

    wsplit_kernel<<<(FDIM * CK) / 512, 512>>>(w);
    xpack_kernel<<<(256 * HW) / 512, 512>>>(x);
    bias_fill_kernel<<<4096, 256>>>(b, (float4*)out);

    dim3 grid(NROI / BN, FDIM / BM);    // (64, 2)
    conv_mma<<<grid, NTHR, SMEM_BYTES>>>(b, roi, out);
}

// round 5
// speedup vs baseline: 3.1458x; 1.0937x over previous
#include <cuda_runtime.h>
#include <cuda_bf16.h>

// ---------------- problem constants ----------------
#define CK     2304
#define HW     16384
#define FDIM   256
#define NROI   8192

// ---------------- GEMM config ----------------
#define BM     128
#define BN     64
#define BK     32
#define NIT    (CK / BK)        // 72
#define NTHR   256

#define APITCH 80               // bytes per smem row (32 bf16 + pad): ldmatrix conflict-free
#define ATILE  (128 * APITCH)   // 10240 B per 128x32 bf16 tile
#define BTILE  (64 * APITCH)    // 5120 B per 64x32 bf16 tile
#define AH_OFF 0
#define AL_OFF ATILE
#define BH_OFF (2 * ATILE)
#define BL_OFF (2 * ATILE + BTILE)
#define STAGE  (2 * ATILE + 2 * BTILE)   // 30720
#define SMEM_BYTES (2 * STAGE)           // 61440

// device scratch (allocation-free)
__device__ __nv_bfloat16 g_whi[FDIM * CK];
__device__ __nv_bfloat16 g_wlo[FDIM * CK];
__device__ unsigned      g_xpk[256 * HW];   // packed {lo16,hi16} of x

// ---------------- PTX helpers ----------------
__device__ __forceinline__ unsigned smem_u32(const void* p) {
    unsigned a;
    asm("{ .reg .u64 t; cvta.to.shared.u64 t, %1; cvt.u32.u64 %0, t; }" : "=r"(a) : "l"(p));
    return a;
}
#define LDSM4(r, a)                                                             \
    asm volatile("ldmatrix.sync.aligned.m8n8.x4.shared.b16 {%0,%1,%2,%3}, [%4];"\
        : "=r"((r)[0]), "=r"((r)[1]), "=r"((r)[2]), "=r"((r)[3]) : "r"(a))
#define MMA16816(c, a, b0, b1)                                                  \
    asm volatile("mma.sync.aligned.m16n8k16.row.col.f32.bf16.bf16.f32 "         \
        "{%0,%1,%2,%3}, {%4,%5,%6,%7}, {%8,%9}, {%0,%1,%2,%3};"                 \
        : "+f"((c)[0]), "+f"((c)[1]), "+f"((c)[2]), "+f"((c)[3])                \
        : "r"((a)[0]), "r"((a)[1]), "r"((a)[2]), "r"((a)[3]), "r"(b0), "r"(b1))
#define STS64(addr, v0, v1)                                                     \
    asm volatile("st.shared.v2.b32 [%0], {%1,%2};" :: "r"(addr), "r"(v0), "r"(v1) : "memory")
#define CPASYNC16(dst, src)                                                     \
    asm volatile("cp.async.cg.shared.global [%0], [%1], 16;" :: "r"(dst), "l"(src))
#define CPCOMMIT() asm volatile("cp.async.commit_group;" ::: "memory")
#define CPWAIT0()  asm volatile("cp.async.wait_group 0;"  ::: "memory")

// ---------------------------------------------------------------------------
// prep kernels
// ---------------------------------------------------------------------------
__global__ __launch_bounds__(512) void wsplit_kernel(const float* __restrict__ w) {
    int i = blockIdx.x * 512 + threadIdx.x;
    float v = w[i];
    __nv_bfloat16 hi = __float2bfloat16(v);
    g_whi[i] = hi;
    g_wlo[i] = __float2bfloat16(v - __bfloat162float(hi));
}

__global__ __launch_bounds__(512) void xpack_kernel(const float* __restrict__ x) {
    int i = blockIdx.x * 512 + threadIdx.x;
    float v = x[i];
    __nv_bfloat16 hi = __float2bfloat16(v);
    __nv_bfloat16 lo = __float2bfloat16(v - __bfloat162float(hi));
    unsigned h = *(unsigned short*)&hi, l = *(unsigned short*)&lo;
    g_xpk[i] = h | (l << 16);
}

__global__ __launch_bounds__(256) void bias_fill_kernel(
    const float* __restrict__ bias, float4* __restrict__ out) {
    int i = blockIdx.x * blockDim.x + threadIdx.x;
    float bv = __ldg(&bias[i >> 12]);
    out[i] = make_float4(bv, bv, bv, bv);
}

// ---------------------------------------------------------------------------
// main: bf16x3 sparse-im2col GEMM via mma.sync m16n8k16
// BM=128 x BN=64 per CTA; 8 warps as 4(m) x 2(n) -> 32x32 per warp; 2 CTAs/SM
// ---------------------------------------------------------------------------
__global__ __launch_bounds__(NTHR, 2) void conv_mma(
    const float* __restrict__ bias, const int* __restrict__ roi,
    float* __restrict__ out)
{
    extern __shared__ char sm[];
    __shared__ int sh_p[BN];
    const unsigned smbase = smem_u32(sm);

    const int tid = threadIdx.x, lane = tid & 31, wid = tid >> 5;
    const int n0 = blockIdx.x * BN, m0g = blockIdx.y * BM;

    if (tid < BN) sh_p[tid] = __ldg(&roi[n0 + tid]);
    __syncthreads();

    // gather-thread constants: thread owns (n = tid&63, kq base = tid>>6)
    const int gn = tid & 63;
    const int gkq0 = tid >> 6;            // 0..3
    const int gp = sh_p[gn];
    const int gh = gp >> 7, gw = gp & 127;

    // warp tile: 4(m) x 2(n) warps -> 32m x 32n per warp
    const int wm = (wid >> 1) * 32, wn = (wid & 1) * 32;
    const int l8 = lane & 7;
    const unsigned a_lane_off =
        (unsigned)((wm + ((lane >> 3) & 1) * 8 + l8) * APITCH + ((lane >> 4) * 8) * 2);
    const unsigned b_lane_off =
        (unsigned)((wn + (lane >> 4) * 8 + l8) * APITCH + (((lane >> 3) & 1) * 8) * 2);

    float acc[2][4][4];
#pragma unroll
    for (int a = 0; a < 2; a++)
#pragma unroll
        for (int b = 0; b < 4; b++)
#pragma unroll
            for (int c = 0; c < 4; c++) acc[a][b][c] = 0.0f;

    unsigned pk[2][4];

    // ---- stage loaders ----
    auto issue_A = [&](int it, int st) {
        const int k0 = it * BK;
        const unsigned dst0 = smbase + st * STAGE;
#pragma unroll
        for (int r = 0; r < 4; r++) {
            int c2 = r * NTHR + tid;           // 0..1023
            int half = c2 >> 9, m = (c2 >> 2) & 127, q = c2 & 3;
            const __nv_bfloat16* src =
                (half ? g_wlo : g_whi) + (m0g + m) * CK + k0 + q * 8;
            CPASYNC16(dst0 + half * ATILE + m * APITCH + q * 16, src);
        }
    };
    auto issue_B = [&](int it) {
        const int k0 = it * BK;
#pragma unroll
        for (int r = 0; r < 2; r++) {
            const int kq = gkq0 + r * 4;       // 0..7
#pragma unroll
            for (int j = 0; j < 4; j++) {
                int kk = k0 + kq * 4 + j;
                unsigned c = ((unsigned)kk * 7282u) >> 16;     // kk/9
                int s9 = kk - (int)c * 9;
                int di = (s9 * 11) >> 5;                       // s9/3
                int dj = s9 - di * 3;
                int hh = gh + di - 1, ww = gw + dj - 1;
                unsigned v = 0u;
                if ((unsigned)hh < 128u && (unsigned)ww < 128u)
                    v = __ldg(&g_xpk[(int)c * HW + hh * 128 + ww]);
                pk[r][j] = v;
            }
        }
    };
    auto store_B = [&](int st) {
        const unsigned dst0 = smbase + st * STAGE;
#pragma unroll
        for (int r = 0; r < 2; r++) {
            const int kq = gkq0 + r * 4;
            unsigned hp0 = __byte_perm(pk[r][0], pk[r][1], 0x5410);
            unsigned hp1 = __byte_perm(pk[r][2], pk[r][3], 0x5410);
            unsigned lp0 = __byte_perm(pk[r][0], pk[r][1], 0x7632);
            unsigned lp1 = __byte_perm(pk[r][2], pk[r][3], 0x7632);
            unsigned off = (unsigned)(gn * APITCH + kq * 8);
            STS64(dst0 + BH_OFF + off, hp0, hp1);
            STS64(dst0 + BL_OFF + off, lp0, lp1);
        }
    };
    auto compute = [&](int st) {
        const unsigned base = smbase + st * STAGE;
#pragma unroll
        for (int k16 = 0; k16 < 2; k16++) {
            unsigned ah[2][4], al[2][4];
#pragma unroll
            for (int mt = 0; mt < 2; mt++) {
                unsigned addr = base + AH_OFF + a_lane_off + mt * 16 * APITCH + k16 * 32;
                LDSM4(ah[mt], addr);
                LDSM4(al[mt], addr + ATILE);
            }
            unsigned bh[2][4], bl[2][4];
#pragma unroll
            for (int np = 0; np < 2; np++) {
                unsigned addr = base + BH_OFF + b_lane_off + np * 16 * APITCH + k16 * 32;
                LDSM4(bh[np], addr);
                LDSM4(bl[np], addr + BTILE);
            }
#pragma unroll
            for (int mt = 0; mt < 2; mt++)
#pragma unroll
                for (int nt = 0; nt < 4; nt++) {
                    int np = nt >> 1, s = (nt & 1) * 2;
                    MMA16816(acc[mt][nt], ah[mt], bh[np][s], bh[np][s + 1]);
                    MMA16816(acc[mt][nt], al[mt], bh[np][s], bh[np][s + 1]);
                    MMA16816(acc[mt][nt], ah[mt], bl[np][s], bl[np][s + 1]);
                }
        }
    };

    // ---- prologue ----
    issue_A(0, 0);
    CPCOMMIT();
    issue_B(0);
    store_B(0);
    CPWAIT0();
    __syncthreads();

    // ---- mainloop (double-buffered) ----
    for (int it = 0; it < NIT; it++) {
        const int cur = it & 1, nxt = cur ^ 1;
        const bool more = (it + 1) < NIT;
        if (more) {
            issue_A(it + 1, nxt);
            CPCOMMIT();
            issue_B(it + 1);
        }
        compute(cur);
        if (more) {
            store_B(nxt);
            CPWAIT0();
        }
        __syncthreads();
    }

    // ---- epilogue: scatter acc + bias ----
#pragma unroll
    for (int mt = 0; mt < 2; mt++) {
        const int f0 = m0g + wm + mt * 16 + (lane >> 2);
        const float b0 = __ldg(&bias[f0]);
        const float b1 = __ldg(&bias[f0 + 8]);
        float* o0 = out + f0 * HW;
        float* o1 = out + (f0 + 8) * HW;
#pragma unroll
        for (int nt = 0; nt < 4; nt++) {
            const int nl = wn + nt * 8 + 2 * (lane & 3);
            const int p0 = sh_p[nl], p1 = sh_p[nl + 1];
            o0[p0] = acc[mt][nt][0] + b0;
            o0[p1] = acc[mt][nt][1] + b0;
            o1[p0] = acc[mt][nt][2] + b1;
            o1[p1] = acc[mt][nt][3] + b1;
        }
    }
}

// ---------------------------------------------------------------------------
extern "C" void kernel_launch(void* const* d_in, const int* in_sizes, int n_in,
                              void* d_out, int out_size)
{
    const float* x   = (const float*)d_in[0];
    const float* w   = (const float*)d_in[1];
    const float* b   = (const float*)d_in[2];
    const int*   roi = (const int*)d_in[3];
    float*       out = (float*)d_out;

    cudaFuncSetAttribute(conv_mma,
                         cudaFuncAttributeMaxDynamicSharedMemorySize, SMEM_BYTES);

    wsplit_kernel<<<(FDIM * CK) / 512, 512>>>(w);
    xpack_kernel<<<(256 * HW) / 512, 512>>>(x);
    bias_fill_kernel<<<4096, 256>>>(b, (float4*)out);

    dim3 grid(NROI / BN, FDIM / BM);    // (128, 2)
    conv_mma<<<grid, NTHR, SMEM_BYTES>>>(b, roi, out);
}